// round 17
// baseline (speedup 1.0000x reference)
#include <cuda_runtime.h>
#include <cuda_bf16.h>

#define MAXN 50000
#define MAXE 800000
#define CH   64
#define NG   64

// ---------------- scratch (device globals) ---------------------------------
__device__ __align__(16) float g_dinv[MAXN];
__device__ __align__(16) float g_selfnorm[MAXN];
__device__ __align__(16) int   g_cnt_i[MAXN];
__device__ __align__(16) int   g_rowptr[MAXN + 1];
__device__ __align__(16) int   g_cursor[MAXN];
__device__ __align__(16) int   g_blocksum[64];
__device__ __align__(16) int2  g_cedge[MAXE];                  // {src, w-as-int-bits}
__device__ __align__(16) __nv_bfloat16 g_hcomb[MAXN * 2 * CH]; // interleaved bf16 (both branches)
__device__ __align__(16) float g_skip[2 * MAXN * CH];
__device__ __align__(16) float g_h   [2 * MAXN * CH];
__device__ __align__(16) float g_pooled[NG * CH];
__device__ __align__(16) float g_cntf[NG];

// ---------------- build CSR ------------------------------------------------

__global__ void k_zero(int n) {
    int i = blockIdx.x * blockDim.x + threadIdx.x;
    if (i < n)       g_cnt_i[i] = 0;
    if (i < NG * CH) g_pooled[i] = 0.0f;
    if (i < NG)      g_cntf[i] = 0.0f;
}

// degree histogram + per-graph node counts fused
__global__ void k_hist(const int* __restrict__ dst, int nE,
                       const int* __restrict__ batch, int n) {
    int e = blockIdx.x * blockDim.x + threadIdx.x;
    if (e < nE) atomicAdd(&g_cnt_i[dst[e]], 1);
    if (e < n)  atomicAdd(&g_cntf[batch[e]], 1.0f);
}

// scan pass 1 (block reduce via shuffles) + dinv/selfnorm fused
__global__ void k_scan_p1(int n) {
    __shared__ int sh[32];
    int i = blockIdx.x * 1024 + threadIdx.x;
    int c = (i < n) ? g_cnt_i[i] : 0;
    if (i < n) {
        float r = rsqrtf((float)c + 1.0f);   // deg incl. self-loop
        g_dinv[i] = r;
        g_selfnorm[i] = r * r;
    }
    int lane = threadIdx.x & 31, wid = threadIdx.x >> 5;
    int s = c;
    #pragma unroll
    for (int o = 16; o > 0; o >>= 1) s += __shfl_down_sync(0xffffffffu, s, o);
    if (lane == 0) sh[wid] = s;
    __syncthreads();
    if (threadIdx.x < 32) {
        int v = sh[threadIdx.x];
        #pragma unroll
        for (int o = 16; o > 0; o >>= 1) v += __shfl_down_sync(0xffffffffu, v, o);
        if (threadIdx.x == 0) g_blocksum[blockIdx.x] = v;
    }
}

// pass 2: shuffle-based block scan; block offset computed in-block (warp 1)
__global__ void k_scan_p3(int n) {
    __shared__ int wsum[32];
    __shared__ int boff;
    int i = blockIdx.x * 1024 + threadIdx.x;
    int v = (i < n) ? g_cnt_i[i] : 0;
    int lane = threadIdx.x & 31, wid = threadIdx.x >> 5;

    int s = v;
    #pragma unroll
    for (int o = 1; o < 32; o <<= 1) {
        int u = __shfl_up_sync(0xffffffffu, s, o);
        if (lane >= o) s += u;
    }
    if (lane == 31) wsum[wid] = s;

    if (wid == 1) {
        int s2 = 0;
        for (int t = lane; t < blockIdx.x; t += 32) s2 += g_blocksum[t];
        #pragma unroll
        for (int o = 16; o > 0; o >>= 1) s2 += __shfl_down_sync(0xffffffffu, s2, o);
        if (lane == 0) boff = s2;
    }
    __syncthreads();

    if (threadIdx.x < 32) {
        int t = wsum[threadIdx.x];
        int ts = t;
        #pragma unroll
        for (int o = 1; o < 32; o <<= 1) {
            int u = __shfl_up_sync(0xffffffffu, ts, o);
            if (lane >= o) ts += u;
        }
        wsum[threadIdx.x] = ts - t;
    }
    __syncthreads();

    int ex = boff + wsum[wid] + s - v;   // exclusive prefix
    if (i < n) { g_rowptr[i] = ex; g_cursor[i] = ex; }
    if (i == n - 1) g_rowptr[n] = ex + v;
}

__global__ void k_place(const int* __restrict__ src, const int* __restrict__ dst, int nE) {
    int e = blockIdx.x * blockDim.x + threadIdx.x;
    if (e >= nE) return;
    int s = src[e], d = dst[e];
    int pos = atomicAdd(&g_cursor[d], 1);
    float w = g_dinv[s] * g_dinv[d];
    g_cedge[pos] = make_int2(s, __float_as_int(w));
}

// ---------------- bf16 helpers ---------------------------------------------
__device__ __forceinline__ uint2 pack_bf16x4(float4 v) {
    __nv_bfloat162 lo = __floats2bfloat162_rn(v.x, v.y);
    __nv_bfloat162 hi = __floats2bfloat162_rn(v.z, v.w);
    uint2 r;
    r.x = *(unsigned*)&lo;
    r.y = *(unsigned*)&hi;
    return r;
}
// exact bf16 -> f32 widening via bit ops (no F2F)
__device__ __forceinline__ float bf_lo(unsigned u) { return __int_as_float((int)(u << 16)); }
__device__ __forceinline__ float bf_hi(unsigned u) { return __int_as_float((int)(u & 0xFFFF0000u)); }

// ---------------- batched GEMM (both branches): X[n,64] @ W[64,64] ---------
// blocks [0, gTile): branch 0; [gTile, 2*gTile): branch 1.
// Writes ONLY the interleaved bf16 mirror HCOMB.
__global__ void k_gemm_b(const float* __restrict__ X1, const float* __restrict__ X2,
                         const float* __restrict__ W1_, const float* __restrict__ W2_,
                         int n, int gTile,
                         __nv_bfloat16* __restrict__ HCOMB)
{
    __shared__ __align__(16) float Ws[64 * 64];
    __shared__ __align__(16) float Xs[64 * 65];

    int tid = threadIdx.x;
    int branch = (blockIdx.x >= gTile) ? 1 : 0;
    int row0 = (blockIdx.x - branch * gTile) * 64;
    const float* X = branch ? X2 : X1;
    const float* W = branch ? W2_ : W1_;

    {
        const float4* W4 = (const float4*)W;
        float4* Ws4 = (float4*)Ws;
        for (int i = tid; i < 1024; i += 256) Ws4[i] = W4[i];
    }
    for (int i = tid; i < 1024; i += 256) {
        int r  = i >> 4;
        int c4 = (i & 15) << 2;
        int gr = row0 + r;
        float4 v = make_float4(0.f, 0.f, 0.f, 0.f);
        if (gr < n) v = *(const float4*)(X + gr * 64 + c4);
        float* p = &Xs[r * 65 + c4];
        p[0] = v.x; p[1] = v.y; p[2] = v.z; p[3] = v.w;
    }
    __syncthreads();

    int tx = tid & 15;
    int ty = tid >> 4;

    float A[4][4] = {};

    #pragma unroll
    for (int k = 0; k < 64; k++) {
        float4 w = *(const float4*)&Ws[k * 64 + tx * 4];
        #pragma unroll
        for (int i = 0; i < 4; i++) {
            float xv = Xs[(ty * 4 + i) * 65 + k];
            A[i][0] = fmaf(xv, w.x, A[i][0]);
            A[i][1] = fmaf(xv, w.y, A[i][1]);
            A[i][2] = fmaf(xv, w.z, A[i][2]);
            A[i][3] = fmaf(xv, w.w, A[i][3]);
        }
    }

    #pragma unroll
    for (int i = 0; i < 4; i++) {
        int r = row0 + ty * 4 + i;
        if (r >= n) break;
        float4 v = make_float4(A[i][0], A[i][1], A[i][2], A[i][3]);
        // interleaved: row = 128 bf16; group tx: [br0 4ch][br1 4ch]
        *(uint2*)(HCOMB + r * 128 + tx * 8 + branch * 4) = pack_bf16x4(v);
    }
}

// ---------------- batched dual GEMM (layer 1): hcomb + fp32 skip -----------
__global__ void k_gemm2_b(const float* __restrict__ X1, const float* __restrict__ X2,
                          const float* __restrict__ Wa1, const float* __restrict__ Wa2,
                          const float* __restrict__ Wb1, const float* __restrict__ Wb2,
                          const float* __restrict__ bb1, const float* __restrict__ bb2,
                          int n, int gTile,
                          __nv_bfloat16* __restrict__ HCOMB,
                          float* __restrict__ OUTb)
{
    __shared__ __align__(16) float Wsa[64 * 64];
    __shared__ __align__(16) float Wsb[64 * 64];
    __shared__ __align__(16) float Xs[64 * 65];

    int tid = threadIdx.x;
    int branch = (blockIdx.x >= gTile) ? 1 : 0;
    int row0 = (blockIdx.x - branch * gTile) * 64;
    const float* X  = branch ? X2  : X1;
    const float* Wa = branch ? Wa2 : Wa1;
    const float* Wb = branch ? Wb2 : Wb1;
    const float* bb = branch ? bb2 : bb1;

    {
        const float4* Wa4 = (const float4*)Wa;
        const float4* Wb4 = (const float4*)Wb;
        float4* a4 = (float4*)Wsa;
        float4* b4 = (float4*)Wsb;
        for (int i = tid; i < 1024; i += 256) { a4[i] = Wa4[i]; b4[i] = Wb4[i]; }
    }
    for (int i = tid; i < 1024; i += 256) {
        int r  = i >> 4;
        int c4 = (i & 15) << 2;
        int gr = row0 + r;
        float4 v = make_float4(0.f, 0.f, 0.f, 0.f);
        if (gr < n) v = *(const float4*)(X + gr * 64 + c4);
        float* p = &Xs[r * 65 + c4];
        p[0] = v.x; p[1] = v.y; p[2] = v.z; p[3] = v.w;
    }
    __syncthreads();

    int tx = tid & 15;
    int ty = tid >> 4;

    float A[4][4] = {}, B[4][4] = {};

    #pragma unroll
    for (int k = 0; k < 64; k++) {
        float4 wa = *(const float4*)&Wsa[k * 64 + tx * 4];
        float4 wb = *(const float4*)&Wsb[k * 64 + tx * 4];
        float xr[4];
        #pragma unroll
        for (int i = 0; i < 4; i++) xr[i] = Xs[(ty * 4 + i) * 65 + k];
        #pragma unroll
        for (int i = 0; i < 4; i++) {
            A[i][0] = fmaf(xr[i], wa.x, A[i][0]);
            A[i][1] = fmaf(xr[i], wa.y, A[i][1]);
            A[i][2] = fmaf(xr[i], wa.z, A[i][2]);
            A[i][3] = fmaf(xr[i], wa.w, A[i][3]);
            B[i][0] = fmaf(xr[i], wb.x, B[i][0]);
            B[i][1] = fmaf(xr[i], wb.y, B[i][1]);
            B[i][2] = fmaf(xr[i], wb.z, B[i][2]);
            B[i][3] = fmaf(xr[i], wb.w, B[i][3]);
        }
    }

    int c0 = tx * 4;
    float4 bv = *(const float4*)(bb + c0);
    #pragma unroll
    for (int i = 0; i < 4; i++) {
        int r = row0 + ty * 4 + i;
        if (r >= n) break;
        float4 va = make_float4(A[i][0], A[i][1], A[i][2], A[i][3]);
        *(uint2*)(HCOMB + r * 128 + tx * 8 + branch * 4) = pack_bf16x4(va);
        *(float4*)(OUTb + (r + branch * n) * 64 + c0) =
            make_float4(fmaxf(B[i][0] + bv.x, 0.f), fmaxf(B[i][1] + bv.y, 0.f),
                        fmaxf(B[i][2] + bv.z, 0.f), fmaxf(B[i][3] + bv.w, 0.f));
    }
}

// ---------------- fused dual-branch GCN aggregate (warp per node) ----------
// 32 threads/node: half-warps walk even/odd edges, shfl_xor(16) combine.
//   o_b[d] = relu( sum_e w_e*Hcomb_b[src_e] + selfnorm[d]*Hcomb_b[d] + bias_b ) + SKIP_b[d]
// if DO_POOL: red-add (o_0 + o_1) into g_pooled[batch[d]].
template<int DO_POOL>
__global__ void k_agg2(const __nv_bfloat16* __restrict__ Hcomb,
                       const float* __restrict__ SKIP,
                       float* __restrict__ OUT,
                       const float* __restrict__ b1_, const float* __restrict__ b2_,
                       const int* __restrict__ batch, int n)
{
    int t = blockIdx.x * blockDim.x + threadIdx.x;
    int node = t >> 5;
    if (node >= n) return;
    int half = (t >> 4) & 1;   // which half-warp
    int g = t & 15;            // channel quad group
    int c4 = g << 2;

    int beg = g_rowptr[node];
    int end = g_rowptr[node + 1];

    const uint4* Hc = (const uint4*)Hcomb;   // 16 uint4 per node row

    float4 acc1, acc2;
    if (half == 0) {
        // self term (bf16, weight = selfnorm) only in half 0
        float sn = g_selfnorm[node];
        uint4 rs = __ldg(&Hc[node * 16 + g]);
        acc1 = make_float4(sn * bf_lo(rs.x), sn * bf_hi(rs.x),
                           sn * bf_lo(rs.y), sn * bf_hi(rs.y));
        acc2 = make_float4(sn * bf_lo(rs.z), sn * bf_hi(rs.z),
                           sn * bf_lo(rs.w), sn * bf_hi(rs.w));
    } else {
        acc1 = make_float4(0.f, 0.f, 0.f, 0.f);
        acc2 = make_float4(0.f, 0.f, 0.f, 0.f);
    }

    // each half-warp walks every other edge; prefetch next-own edge
    int j0 = beg + half;
    int2 e = (j0 < end) ? __ldg(&g_cedge[j0]) : make_int2(0, 0);
    for (int j = j0; j < end; j += 2) {
        int2 e_cur = e;
        if (j + 2 < end) e = __ldg(&g_cedge[j + 2]);
        float w = __int_as_float(e_cur.y);
        uint4 raw = __ldg(&Hc[e_cur.x * 16 + g]);   // 16B: br1 4ch + br2 4ch
        acc1.x = fmaf(w, bf_lo(raw.x), acc1.x);
        acc1.y = fmaf(w, bf_hi(raw.x), acc1.y);
        acc1.z = fmaf(w, bf_lo(raw.y), acc1.z);
        acc1.w = fmaf(w, bf_hi(raw.y), acc1.w);
        acc2.x = fmaf(w, bf_lo(raw.z), acc2.x);
        acc2.y = fmaf(w, bf_hi(raw.z), acc2.y);
        acc2.z = fmaf(w, bf_lo(raw.w), acc2.z);
        acc2.w = fmaf(w, bf_hi(raw.w), acc2.w);
    }

    // combine the two halves (same g in the other half-warp is lane^16)
    acc1.x += __shfl_xor_sync(0xffffffffu, acc1.x, 16);
    acc1.y += __shfl_xor_sync(0xffffffffu, acc1.y, 16);
    acc1.z += __shfl_xor_sync(0xffffffffu, acc1.z, 16);
    acc1.w += __shfl_xor_sync(0xffffffffu, acc1.w, 16);
    acc2.x += __shfl_xor_sync(0xffffffffu, acc2.x, 16);
    acc2.y += __shfl_xor_sync(0xffffffffu, acc2.y, 16);
    acc2.z += __shfl_xor_sync(0xffffffffu, acc2.z, 16);
    acc2.w += __shfl_xor_sync(0xffffffffu, acc2.w, 16);

    if (half == 0) {
        float4 bv1 = *(const float4*)(b1_ + c4);
        float4 bv2 = *(const float4*)(b2_ + c4);
        float4 sk1 = *(const float4*)(SKIP + node * 64 + c4);
        float4 sk2 = *(const float4*)(SKIP + (node + n) * 64 + c4);
        float4 o1 = make_float4(fmaxf(acc1.x + bv1.x, 0.f) + sk1.x,
                                fmaxf(acc1.y + bv1.y, 0.f) + sk1.y,
                                fmaxf(acc1.z + bv1.z, 0.f) + sk1.z,
                                fmaxf(acc1.w + bv1.w, 0.f) + sk1.w);
        float4 o2 = make_float4(fmaxf(acc2.x + bv2.x, 0.f) + sk2.x,
                                fmaxf(acc2.y + bv2.y, 0.f) + sk2.y,
                                fmaxf(acc2.z + bv2.z, 0.f) + sk2.z,
                                fmaxf(acc2.w + bv2.w, 0.f) + sk2.w);
        *(float4*)(OUT + node * 64 + c4) = o1;
        *(float4*)(OUT + (node + n) * 64 + c4) = o2;

        if (DO_POOL) {
            int gi = batch[node];
            float* p = g_pooled + gi * 64 + c4;
            asm volatile("red.global.add.v4.f32 [%0], {%1,%2,%3,%4};"
                         :: "l"(p), "f"(o1.x + o2.x), "f"(o1.y + o2.y),
                            "f"(o1.z + o2.z), "f"(o1.w + o2.w)
                         : "memory");
        }
    }
}

__global__ void k_final(const float* __restrict__ Wf, const float* __restrict__ bf,
                        float* __restrict__ out)
{
    int g = threadIdx.x;
    if (g >= NG) return;
    float cnt = fmaxf(g_cntf[g], 1.0f);
    float acc = 0.f;
    #pragma unroll
    for (int c = 0; c < CH; c++) acc += g_pooled[g * CH + c] * Wf[c];
    out[g] = acc / cnt + bf[0];
}

// ---------------- host -----------------------------------------------------

extern "C" void kernel_launch(void* const* d_in, const int* in_sizes, int n_in,
                              void* d_out, int out_size)
{
    const float* x   = (const float*)d_in[0];
    const float* xsc = (const float*)d_in[1];
    const float* W1  = (const float*)d_in[2];
    const float* b1  = (const float*)d_in[3];
    const float* W2  = (const float*)d_in[4];
    const float* b2  = (const float*)d_in[5];
    const float* We  = (const float*)d_in[6];
    const float* be  = (const float*)d_in[7];
    const float* W1s = (const float*)d_in[8];
    const float* b1s = (const float*)d_in[9];
    const float* W2s = (const float*)d_in[10];
    const float* b2s = (const float*)d_in[11];
    const float* Wes = (const float*)d_in[12];
    const float* bes = (const float*)d_in[13];
    const float* Wf  = (const float*)d_in[14];
    const float* bf  = (const float*)d_in[15];
    const int*   ei  = (const int*)d_in[16];
    const int*   bat = (const int*)d_in[17];

    int n  = in_sizes[0] / CH;
    int nE = in_sizes[16] / 2;
    const int* src = ei;
    const int* dst = ei + nE;
    float* out = (float*)d_out;

    float *skip, *h;
    __nv_bfloat16* hcomb;
    cudaGetSymbolAddress((void**)&hcomb, g_hcomb);
    cudaGetSymbolAddress((void**)&skip,  g_skip);
    cudaGetSymbolAddress((void**)&h,     g_h);

    const int T = 256;
    int gN     = (n + T - 1) / T;
    int gE     = (nE + T - 1) / T;
    int gTile  = (n + 63) / 64;
    int gN32   = ((long long)n * 32 + T - 1) / T;
    int nB     = (n + 1023) / 1024;

    // CSR build
    k_zero<<<gN, T>>>(n);
    k_hist<<<gE, T>>>(dst, nE, bat, n);
    k_scan_p1<<<nB, 1024>>>(n);
    k_scan_p3<<<nB, 1024>>>(n);
    k_place<<<gE, T>>>(src, dst, nE);

    // ---- layer 1 (both branches batched) ----
    k_gemm2_b<<<2 * gTile, T>>>(x, xsc, W1, W1s, We, Wes, be, bes,
                                n, gTile, hcomb, skip);
    k_agg2<0><<<gN32, T>>>(hcomb, skip, h, b1, b1s, bat, n);

    // ---- layer 2 (both branches batched) ----
    k_gemm_b<<<2 * gTile, T>>>(h, h + (size_t)n * CH, W2, W2s,
                               n, gTile, hcomb);
    k_agg2<1><<<gN32, T>>>(hcomb, h, h, b2, b2s, bat, n);

    k_final<<<1, 64>>>(Wf, bf, out);
}